// round 10
// baseline (speedup 1.0000x reference)
#include <cuda_runtime.h>
#include <math.h>

#define F 256
#define NB 1024            // B=65536 -> exactly 64 rows per block

// Stage-1 partials, transposed: [F][NB] float4 = 4 MB
__device__ float4 g_part[F * NB];
__device__ double g_bits[F];

__device__ __forceinline__ float fast_lg2(float a) {
    float r; asm("lg2.approx.f32 %0, %1;" : "=f"(r) : "f"(a)); return r;
}
__device__ __forceinline__ float fast_ex2(float a) {
    float r; asm("ex2.approx.f32 %0, %1;" : "=f"(r) : "f"(a)); return r;
}

template<int ROWS>
__global__ void __launch_bounds__(256) mdl_pass1(
    const float* __restrict__ res,
    const float* __restrict__ lambda1,
    const float* __restrict__ lambda2,
    int rows_rt)
{
    const int f = threadIdx.x;            // feature 0..255
    const float l1 = lambda1[f];
    const float l2 = lambda2[f];
    // clamp lambdas away from 0 (tiny case flows through the same path)
    float lamP = (fabsf(l1) < 1e-8f) ? 1e-8f : l1;
    float lamN = 2.0f - l2;
    if (fabsf(lamN) < 1e-8f) lamN = 1e-8f;
    const float rlamP  =  1.0f / lamP;
    const float nrlamN = -1.0f / lamN;
    // single-interval safety: safe == (loB < x <= hiB); bad-lambda flags folded in
    const float hiB = (fabsf(l1) <= 1.9f) ? 1000.0f : -0.0f;
    const float loB = (fabsf(l2) <= 1.9f) ? -0.99f  :  0.0f;

    const int rows = (ROWS > 0) ? ROWS : rows_rt;
    const float* p = res + (size_t)blockIdx.x * rows * F + f;

    float cnt = 0.0f, sy = 0.0f, sy2 = 0.0f, slj2 = 0.0f;

    const int nb8 = rows >> 3;
    for (int b = 0; b < nb8; ++b) {
        // batch loads first: MLP=8, immediate-offset LDG
        float xb[8];
#pragma unroll
        for (int i = 0; i < 8; ++i)
            xb[i] = __ldcs(p + (b * 8 + i) * F);

#pragma unroll
        for (int i = 0; i < 8; ++i) {
            const float x = xb[i];
            const bool pos = (x >= 0.0f);

            // pos clip at 1000 dropped (those elements are masked -> exact);
            // neg clamp at -0.989 kept (affects the safe band (-0.99,-0.989]).
            const float a  = 1.0f + fabsf(fmaxf(x, -0.989f));
            const float t2 = fast_lg2(a);                  // log2(1+|x|clip)
            const float lam = pos ? lamP : lamN;
            const float u2  = lam * t2;
            const float ee  = fast_ex2(u2);
            const float rl  = pos ? rlamP : nrlamN;        // sign folded in
            const float y   = fmaf(ee, rl, -rl);           // (2^u2 - 1) * rl

            // branchless masked accumulation — no BSSY/BSYNC, no divergence
            const float m  = ((x > loB) && (x <= hiB)) ? 1.0f : 0.0f;
            const float my = m * y;
            cnt  += m;
            sy   += my;
            sy2   = fmaf(my, y, sy2);
            slj2  = fmaf(m, u2 - t2, slj2);                // log_jac / ln2
        }
    }

    g_part[f * NB + blockIdx.x] = make_float4(cnt, sy, sy2, slj2);  // one STG.128
}

// 128 blocks x 256 threads. Block j owns features 2j (warps 0-3) and 2j+1
// (warps 4-7). Each warp reduces a quarter (256) of the NB float4 entries
// (one LDG.128 per entry); smem combine; one thread per feature finishes the
// double-precision bit math.
__global__ __launch_bounds__(256) void mdl_pass2a(
    const float* __restrict__ resolutions, int B)
{
    const int w    = threadIdx.x >> 5;       // 0..7
    const int lane = threadIdx.x & 31;
    const int gf   = blockIdx.x * 2 + (w >> 2);
    const int wq   = w & 3;                  // quarter index

    const float4* b0 = g_part + (size_t)gf * NB;
    const int bbeg = wq * (NB / 4);
    const int bend = bbeg + (NB / 4);

    double cnt = 0.0, sy = 0.0, sy2 = 0.0, slj = 0.0;
#pragma unroll 4
    for (int b = bbeg + lane; b < bend; b += 32) {
        const float4 v = b0[b];
        cnt += (double)v.x;
        sy  += (double)v.y;
        sy2 += (double)v.z;
        slj += (double)v.w;
    }
#pragma unroll
    for (int o = 16; o > 0; o >>= 1) {
        cnt += __shfl_down_sync(0xffffffffu, cnt, o);
        sy  += __shfl_down_sync(0xffffffffu, sy,  o);
        sy2 += __shfl_down_sync(0xffffffffu, sy2, o);
        slj += __shfl_down_sync(0xffffffffu, slj, o);
    }

    __shared__ double sh[8][4];
    if (lane == 0) { sh[w][0] = cnt; sh[w][1] = sy; sh[w][2] = sy2; sh[w][3] = slj; }
    __syncthreads();

    if ((threadIdx.x & 127) == 0) {          // thread 0 and thread 128
        const int wb = (w >> 2) * 4;
        cnt = sh[wb][0] + sh[wb+1][0] + sh[wb+2][0] + sh[wb+3][0];
        sy  = sh[wb][1] + sh[wb+1][1] + sh[wb+2][1] + sh[wb+3][1];
        sy2 = sh[wb][2] + sh[wb+1][2] + sh[wb+2][2] + sh[wb+3][2];
        slj = sh[wb][3] + sh[wb+1][3] + sh[wb+2][3] + sh[wb+3][3];

        const double LN2 = 0.6931471805599453;
        const double LOG2_2PIE = 2.0470955851806783;

        const double Bd    = (double)B;
        const double nf    = cnt;
        const double nexc  = Bd - nf;
        const double denom = fmax(nf, 1.0);
        const double mean  = sy / denom;
        double var = (sy2 - 2.0 * mean * sy + mean * mean * nf) / denom;
        var = fmax(var, 1e-12);

        const double diff_bits = (nf > 1.0) ? nf * (LOG2_2PIE + 0.5 * log2(var)) : 0.0;
        const double jac_bits  = slj;        // already in log2 units
        const double rres      = (double)resolutions[gf];
        const double exc_bits  = (nexc > 0.0) ? nexc * (-log2(rres)) : 0.0;
        const double log_binom = lgamma(Bd + 1.0) - lgamma(nexc + 1.0)
                               - lgamma(Bd - nexc + 1.0);
        const double part_bits = (nexc > 0.0 && nexc < Bd) ? (log_binom / LN2) : 0.0;
        const double lambda_bits = 2.0 * (log(100.0) / LN2);

        g_bits[gf] = diff_bits + jac_bits + exc_bits + part_bits + lambda_bits;
    }
}

__global__ __launch_bounds__(256) void mdl_pass2b(float* __restrict__ out)
{
    const int f = threadIdx.x;
    __shared__ double sh[F];
    sh[f] = g_bits[f];
    __syncthreads();
#pragma unroll
    for (int s = 128; s > 0; s >>= 1) {
        if (f < s) sh[f] += sh[f + s];
        __syncthreads();
    }
    if (f == 0) out[0] = (float)sh[0];
}

extern "C" void kernel_launch(void* const* d_in, const int* in_sizes, int n_in,
                              void* d_out, int out_size)
{
    const float* residuals   = (const float*)d_in[0];
    const float* lambda1     = (const float*)d_in[1];
    const float* lambda2     = (const float*)d_in[2];
    const float* resolutions = (const float*)d_in[3];
    float* out = (float*)d_out;

    const int B = in_sizes[0] / F;

    if (B == NB * 64) {
        mdl_pass1<64><<<NB, 256>>>(residuals, lambda1, lambda2, 64);
    } else {
        const int rows = (B + NB - 1) / NB;   // assumes B % (NB*8) == 0
        mdl_pass1<0><<<NB, 256>>>(residuals, lambda1, lambda2, rows);
    }
    mdl_pass2a<<<F / 2, 256>>>(resolutions, B);
    mdl_pass2b<<<1, 256>>>(out);
}

// round 11
// speedup vs baseline: 1.0924x; 1.0924x over previous
#include <cuda_runtime.h>
#include <math.h>

#define F 256
#define NB 1024            // row-chunks: B=65536 -> exactly 64 rows per chunk

// Stage-1 partials, transposed: [F][NB] float4 = 4 MB
__device__ float4 g_part[F * NB];
__device__ double g_bits[F];

__device__ __forceinline__ float fast_lg2(float a) {
    float r; asm("lg2.approx.f32 %0, %1;" : "=f"(r) : "f"(a)); return r;
}
__device__ __forceinline__ float fast_ex2(float a) {
    float r; asm("ex2.approx.f32 %0, %1;" : "=f"(r) : "f"(a)); return r;
}

// 128-thread CTAs: grid = NB*2. CTA covers 64 rows x 128 features.
//   chunk = blockIdx.x >> 1   (row chunk, 0..NB-1)
//   f     = (blockIdx.x & 1) * 128 + threadIdx.x
// 16 CTAs/SM capacity (32 regs x 128 thr x 16 = 64K regs) -> ~86% residency
// at grid 2048 vs 6.92/8 with 256-thread CTAs.
template<int ROWS>
__global__ void __launch_bounds__(128) mdl_pass1(
    const float* __restrict__ res,
    const float* __restrict__ lambda1,
    const float* __restrict__ lambda2,
    int rows_rt)
{
    const int chunk = blockIdx.x >> 1;
    const int f = ((blockIdx.x & 1) << 7) + threadIdx.x;   // feature 0..255
    const float l1 = lambda1[f];
    const float l2 = lambda2[f];
    // clamp lambdas away from 0 (tiny case flows through the same path)
    float lamP = (fabsf(l1) < 1e-8f) ? 1e-8f : l1;
    float lamN = 2.0f - l2;
    if (fabsf(lamN) < 1e-8f) lamN = 1e-8f;
    const float rlamP  =  1.0f / lamP;
    const float nrlamN = -1.0f / lamN;
    // single-interval safety: safe == (loB < x <= hiB); bad-lambda flags folded in
    const float hiB = (fabsf(l1) <= 1.9f) ? 1000.0f : -0.0f;
    const float loB = (fabsf(l2) <= 1.9f) ? -0.99f  :  0.0f;

    const int rows = (ROWS > 0) ? ROWS : rows_rt;
    const float* p = res + (size_t)chunk * rows * F + f;

    float cnt = 0.0f, sy = 0.0f, sy2 = 0.0f, slj2 = 0.0f;

#pragma unroll 8
    for (int r = 0; r < rows; ++r) {
        const float x = __ldcs(p + r * F);       // LDG [base+imm]
        const bool pos = (x >= 0.0f);

        // pos clip at 1000 dropped (those elements are masked -> exact);
        // neg clamp at -0.989 kept (affects the safe band (-0.99,-0.989]).
        const float a  = 1.0f + fabsf(fmaxf(x, -0.989f));
        const float t2 = fast_lg2(a);                    // log2(1+|x|clip)
        const float lam = pos ? lamP : lamN;
        const float u2  = lam * t2;
        const float ee  = fast_ex2(u2);
        const float rl  = pos ? rlamP : nrlamN;          // sign folded in
        const float y   = fmaf(ee, rl, -rl);             // (2^u2 - 1) * rl

        const bool safe = (x > loB) && (x <= hiB);
        if (safe) {
            cnt  += 1.0f;
            sy   += y;
            sy2   = fmaf(y, y, sy2);
            slj2 += (u2 - t2);                           // log_jac / ln2
        }
    }

    g_part[f * NB + chunk] = make_float4(cnt, sy, sy2, slj2);   // one STG.128
}

// 128 blocks x 256 threads. Block j owns features 2j (warps 0-3) and 2j+1
// (warps 4-7). Each warp reduces a quarter (256) of the NB float4 entries
// (one LDG.128 per entry); smem combine; one thread per feature finishes the
// double-precision bit math.
__global__ __launch_bounds__(256) void mdl_pass2a(
    const float* __restrict__ resolutions, int B)
{
    const int w    = threadIdx.x >> 5;       // 0..7
    const int lane = threadIdx.x & 31;
    const int gf   = blockIdx.x * 2 + (w >> 2);
    const int wq   = w & 3;                  // quarter index

    const float4* b0 = g_part + (size_t)gf * NB;
    const int bbeg = wq * (NB / 4);
    const int bend = bbeg + (NB / 4);

    double cnt = 0.0, sy = 0.0, sy2 = 0.0, slj = 0.0;
#pragma unroll 4
    for (int b = bbeg + lane; b < bend; b += 32) {
        const float4 v = b0[b];
        cnt += (double)v.x;
        sy  += (double)v.y;
        sy2 += (double)v.z;
        slj += (double)v.w;
    }
#pragma unroll
    for (int o = 16; o > 0; o >>= 1) {
        cnt += __shfl_down_sync(0xffffffffu, cnt, o);
        sy  += __shfl_down_sync(0xffffffffu, sy,  o);
        sy2 += __shfl_down_sync(0xffffffffu, sy2, o);
        slj += __shfl_down_sync(0xffffffffu, slj, o);
    }

    __shared__ double sh[8][4];
    if (lane == 0) { sh[w][0] = cnt; sh[w][1] = sy; sh[w][2] = sy2; sh[w][3] = slj; }
    __syncthreads();

    if ((threadIdx.x & 127) == 0) {          // thread 0 and thread 128
        const int wb = (w >> 2) * 4;
        cnt = sh[wb][0] + sh[wb+1][0] + sh[wb+2][0] + sh[wb+3][0];
        sy  = sh[wb][1] + sh[wb+1][1] + sh[wb+2][1] + sh[wb+3][1];
        sy2 = sh[wb][2] + sh[wb+1][2] + sh[wb+2][2] + sh[wb+3][2];
        slj = sh[wb][3] + sh[wb+1][3] + sh[wb+2][3] + sh[wb+3][3];

        const double LN2 = 0.6931471805599453;
        const double LOG2_2PIE = 2.0470955851806783;

        const double Bd    = (double)B;
        const double nf    = cnt;
        const double nexc  = Bd - nf;
        const double denom = fmax(nf, 1.0);
        const double mean  = sy / denom;
        double var = (sy2 - 2.0 * mean * sy + mean * mean * nf) / denom;
        var = fmax(var, 1e-12);

        const double diff_bits = (nf > 1.0) ? nf * (LOG2_2PIE + 0.5 * log2(var)) : 0.0;
        const double jac_bits  = slj;        // already in log2 units
        const double rres      = (double)resolutions[gf];
        const double exc_bits  = (nexc > 0.0) ? nexc * (-log2(rres)) : 0.0;
        const double log_binom = lgamma(Bd + 1.0) - lgamma(nexc + 1.0)
                               - lgamma(Bd - nexc + 1.0);
        const double part_bits = (nexc > 0.0 && nexc < Bd) ? (log_binom / LN2) : 0.0;
        const double lambda_bits = 2.0 * (log(100.0) / LN2);

        g_bits[gf] = diff_bits + jac_bits + exc_bits + part_bits + lambda_bits;
    }
}

__global__ __launch_bounds__(256) void mdl_pass2b(float* __restrict__ out)
{
    const int f = threadIdx.x;
    __shared__ double sh[F];
    sh[f] = g_bits[f];
    __syncthreads();
#pragma unroll
    for (int s = 128; s > 0; s >>= 1) {
        if (f < s) sh[f] += sh[f + s];
        __syncthreads();
    }
    if (f == 0) out[0] = (float)sh[0];
}

extern "C" void kernel_launch(void* const* d_in, const int* in_sizes, int n_in,
                              void* d_out, int out_size)
{
    const float* residuals   = (const float*)d_in[0];
    const float* lambda1     = (const float*)d_in[1];
    const float* lambda2     = (const float*)d_in[2];
    const float* resolutions = (const float*)d_in[3];
    float* out = (float*)d_out;

    const int B = in_sizes[0] / F;

    if (B == NB * 64) {
        mdl_pass1<64><<<NB * 2, 128>>>(residuals, lambda1, lambda2, 64);
    } else {
        const int rows = (B + NB - 1) / NB;   // assumes B % NB == 0
        mdl_pass1<0><<<NB * 2, 128>>>(residuals, lambda1, lambda2, rows);
    }
    mdl_pass2a<<<F / 2, 256>>>(resolutions, B);
    mdl_pass2b<<<1, 256>>>(out);
}

// round 12
// speedup vs baseline: 1.1066x; 1.0130x over previous
#include <cuda_runtime.h>
#include <math.h>

#define F 256
#define NB 512             // row-chunks: B=65536 -> exactly 128 rows per chunk

// Stage-1 partials, transposed: [F][NB] float4 = 2 MB
__device__ float4 g_part[F * NB];
__device__ double g_bits[F];

__device__ __forceinline__ float fast_lg2(float a) {
    float r; asm("lg2.approx.f32 %0, %1;" : "=f"(r) : "f"(a)); return r;
}
__device__ __forceinline__ float fast_ex2(float a) {
    float r; asm("ex2.approx.f32 %0, %1;" : "=f"(r) : "f"(a)); return r;
}

// 128-thread CTAs: grid = NB*2. CTA covers 128 rows x 128 features.
//   chunk = blockIdx.x >> 1   (row chunk, 0..NB-1)
//   f     = (blockIdx.x & 1) * 128 + threadIdx.x
template<int ROWS>
__global__ void __launch_bounds__(128) mdl_pass1(
    const float* __restrict__ res,
    const float* __restrict__ lambda1,
    const float* __restrict__ lambda2,
    int rows_rt)
{
    const int chunk = blockIdx.x >> 1;
    const int f = ((blockIdx.x & 1) << 7) + threadIdx.x;   // feature 0..255
    const float l1 = lambda1[f];
    const float l2 = lambda2[f];
    // clamp lambdas away from 0 (tiny case flows through the same path)
    float lamP = (fabsf(l1) < 1e-8f) ? 1e-8f : l1;
    float lamN = 2.0f - l2;
    if (fabsf(lamN) < 1e-8f) lamN = 1e-8f;
    const float rlamP  =  1.0f / lamP;
    const float nrlamN = -1.0f / lamN;
    // single-interval safety: safe == (loB < x <= hiB); bad-lambda flags folded in
    const float hiB = (fabsf(l1) <= 1.9f) ? 1000.0f : -0.0f;
    const float loB = (fabsf(l2) <= 1.9f) ? -0.99f  :  0.0f;

    const int rows = (ROWS > 0) ? ROWS : rows_rt;
    const float* p = res + (size_t)chunk * rows * F + f;

    float cnt = 0.0f, sy = 0.0f, sy2 = 0.0f, slj2 = 0.0f;

#pragma unroll 8
    for (int r = 0; r < rows; ++r) {
        const float x = __ldcs(p + r * F);       // LDG [base+imm]
        const bool pos = (x >= 0.0f);

        // pos clip at 1000 dropped (those elements are masked -> exact);
        // neg clamp at -0.989 kept (affects the safe band (-0.99,-0.989]).
        const float a  = 1.0f + fabsf(fmaxf(x, -0.989f));
        const float t2 = fast_lg2(a);                    // log2(1+|x|clip)
        const float lam = pos ? lamP : lamN;
        const float u2  = lam * t2;
        const float ee  = fast_ex2(u2);
        const float rl  = pos ? rlamP : nrlamN;          // sign folded in
        const float y   = fmaf(ee, rl, -rl);             // (2^u2 - 1) * rl

        const bool safe = (x > loB) && (x <= hiB);
        if (safe) {
            cnt  += 1.0f;
            sy   += y;
            sy2   = fmaf(y, y, sy2);
            slj2 += (u2 - t2);                           // log_jac / ln2
        }
    }

    g_part[f * NB + chunk] = make_float4(cnt, sy, sy2, slj2);   // one STG.128
}

// 128 blocks x 256 threads. Block j owns features 2j (warps 0-3) and 2j+1
// (warps 4-7). Each warp reduces a quarter (128) of the NB float4 entries
// (one LDG.128 per entry); smem combine; one thread per feature finishes the
// double-precision bit math.
__global__ __launch_bounds__(256) void mdl_pass2a(
    const float* __restrict__ resolutions, int B)
{
    const int w    = threadIdx.x >> 5;       // 0..7
    const int lane = threadIdx.x & 31;
    const int gf   = blockIdx.x * 2 + (w >> 2);
    const int wq   = w & 3;                  // quarter index

    const float4* b0 = g_part + (size_t)gf * NB;
    const int bbeg = wq * (NB / 4);
    const int bend = bbeg + (NB / 4);

    double cnt = 0.0, sy = 0.0, sy2 = 0.0, slj = 0.0;
#pragma unroll 4
    for (int b = bbeg + lane; b < bend; b += 32) {
        const float4 v = b0[b];
        cnt += (double)v.x;
        sy  += (double)v.y;
        sy2 += (double)v.z;
        slj += (double)v.w;
    }
#pragma unroll
    for (int o = 16; o > 0; o >>= 1) {
        cnt += __shfl_down_sync(0xffffffffu, cnt, o);
        sy  += __shfl_down_sync(0xffffffffu, sy,  o);
        sy2 += __shfl_down_sync(0xffffffffu, sy2, o);
        slj += __shfl_down_sync(0xffffffffu, slj, o);
    }

    __shared__ double sh[8][4];
    if (lane == 0) { sh[w][0] = cnt; sh[w][1] = sy; sh[w][2] = sy2; sh[w][3] = slj; }
    __syncthreads();

    if ((threadIdx.x & 127) == 0) {          // thread 0 and thread 128
        const int wb = (w >> 2) * 4;
        cnt = sh[wb][0] + sh[wb+1][0] + sh[wb+2][0] + sh[wb+3][0];
        sy  = sh[wb][1] + sh[wb+1][1] + sh[wb+2][1] + sh[wb+3][1];
        sy2 = sh[wb][2] + sh[wb+1][2] + sh[wb+2][2] + sh[wb+3][2];
        slj = sh[wb][3] + sh[wb+1][3] + sh[wb+2][3] + sh[wb+3][3];

        const double LN2 = 0.6931471805599453;
        const double LOG2_2PIE = 2.0470955851806783;

        const double Bd    = (double)B;
        const double nf    = cnt;
        const double nexc  = Bd - nf;
        const double denom = fmax(nf, 1.0);
        const double mean  = sy / denom;
        double var = (sy2 - 2.0 * mean * sy + mean * mean * nf) / denom;
        var = fmax(var, 1e-12);

        const double diff_bits = (nf > 1.0) ? nf * (LOG2_2PIE + 0.5 * log2(var)) : 0.0;
        const double jac_bits  = slj;        // already in log2 units
        const double rres      = (double)resolutions[gf];
        const double exc_bits  = (nexc > 0.0) ? nexc * (-log2(rres)) : 0.0;
        const double log_binom = lgamma(Bd + 1.0) - lgamma(nexc + 1.0)
                               - lgamma(Bd - nexc + 1.0);
        const double part_bits = (nexc > 0.0 && nexc < Bd) ? (log_binom / LN2) : 0.0;
        const double lambda_bits = 2.0 * (log(100.0) / LN2);

        g_bits[gf] = diff_bits + jac_bits + exc_bits + part_bits + lambda_bits;
    }
}

__global__ __launch_bounds__(256) void mdl_pass2b(float* __restrict__ out)
{
    const int f = threadIdx.x;
    __shared__ double sh[F];
    sh[f] = g_bits[f];
    __syncthreads();
#pragma unroll
    for (int s = 128; s > 0; s >>= 1) {
        if (f < s) sh[f] += sh[f + s];
        __syncthreads();
    }
    if (f == 0) out[0] = (float)sh[0];
}

extern "C" void kernel_launch(void* const* d_in, const int* in_sizes, int n_in,
                              void* d_out, int out_size)
{
    const float* residuals   = (const float*)d_in[0];
    const float* lambda1     = (const float*)d_in[1];
    const float* lambda2     = (const float*)d_in[2];
    const float* resolutions = (const float*)d_in[3];
    float* out = (float*)d_out;

    const int B = in_sizes[0] / F;

    if (B == NB * 128) {
        mdl_pass1<128><<<NB * 2, 128>>>(residuals, lambda1, lambda2, 128);
    } else {
        const int rows = (B + NB - 1) / NB;   // assumes B % NB == 0
        mdl_pass1<0><<<NB * 2, 128>>>(residuals, lambda1, lambda2, rows);
    }
    mdl_pass2a<<<F / 2, 256>>>(resolutions, B);
    mdl_pass2b<<<1, 256>>>(out);
}